// round 1
// baseline (speedup 1.0000x reference)
#include <cuda_runtime.h>
#include <math.h>
#include <stdint.h>

// Problem constants
#define N_TOK   524288      // N*P total rows
#define P_TOK   64
#define C_DIM   128
#define M_PART  4096
#define MW_CNT  262144
#define A_CNT   131072
#define BL_CNT  65536
#define EPS_LN  1e-6f

// Scratch (device globals — allocation-free rule)
__device__ float g_xa[(size_t)A_CNT * C_DIM];    // double-LN'd asy rows (rank order)
__device__ float g_att[(size_t)A_CNT * C_DIM];   // attention+proj output for asy rows (rank order)
__device__ unsigned char g_flag[MW_CNT];         // 0 = neither, 1 = asy, 2 = blocked
__device__ int g_rank[MW_CNT];                   // rank within asy_index for flag==1

__device__ __forceinline__ float warp_sum(float v) {
#pragma unroll
    for (int o = 16; o; o >>= 1) v += __shfl_xor_sync(0xffffffffu, v, o);
    return v;
}
__device__ __forceinline__ float warp_max(float v) {
#pragma unroll
    for (int o = 16; o; o >>= 1) v = fmaxf(v, __shfl_xor_sync(0xffffffffu, v, o));
    return v;
}

// ---------------------------------------------------------------------------
// K1: X = LN(x) for all rows -> d_out. One warp per 128-wide row, float4 lanes.
// ---------------------------------------------------------------------------
__global__ void __launch_bounds__(256) ln_kernel(
    const float* __restrict__ x,
    const float* __restrict__ w, const float* __restrict__ b,
    float* __restrict__ out)
{
    int row  = (int)((blockIdx.x * 256u + threadIdx.x) >> 5);
    int lane = threadIdx.x & 31;
    if (row >= N_TOK) return;
    float4 v = reinterpret_cast<const float4*>(x + (size_t)row * C_DIM)[lane];
    float m = warp_sum(v.x + v.y + v.z + v.w) * (1.0f / C_DIM);
    float dx = v.x - m, dy = v.y - m, dz = v.z - m, dw = v.w - m;
    float var = warp_sum(dx*dx + dy*dy + dz*dz + dw*dw) * (1.0f / C_DIM);
    float inv = rsqrtf(var + EPS_LN);
    float4 wv = reinterpret_cast<const float4*>(w)[lane];
    float4 bv = reinterpret_cast<const float4*>(b)[lane];
    float4 r;
    r.x = dx * inv * wv.x + bv.x;
    r.y = dy * inv * wv.y + bv.y;
    r.z = dz * inv * wv.z + bv.z;
    r.w = dw * inv * wv.w + bv.w;
    reinterpret_cast<float4*>(out + (size_t)row * C_DIM)[lane] = r;
}

// ---------------------------------------------------------------------------
// K2/K3: flag + rank maps
// ---------------------------------------------------------------------------
__global__ void __launch_bounds__(256) zero_flags_kernel()
{
    int t = blockIdx.x * 256 + threadIdx.x;
    if (t < MW_CNT / 16)
        reinterpret_cast<uint4*>(g_flag)[t] = make_uint4(0u, 0u, 0u, 0u);
}

__global__ void __launch_bounds__(256) set_flags_kernel(
    const int* __restrict__ asy, const int* __restrict__ blk)
{
    int t = blockIdx.x * 256 + threadIdx.x;
    if (t < A_CNT) {
        int g = asy[t];
        g_flag[g] = 1;
        g_rank[g] = t;
    } else if (t < A_CNT + BL_CNT) {
        g_flag[blk[t - A_CNT]] = 2;
    }
}

// ---------------------------------------------------------------------------
// K4: xa = LN(X[window pos of asy_index[i]]) -> g_xa. One warp per row.
// ---------------------------------------------------------------------------
__global__ void __launch_bounds__(256) xa_kernel(
    const float* __restrict__ X, const int* __restrict__ asy,
    const int* __restrict__ iw,
    const float* __restrict__ w, const float* __restrict__ b)
{
    int i    = (int)((blockIdx.x * 256u + threadIdx.x) >> 5);
    int lane = threadIdx.x & 31;
    if (i >= A_CNT) return;
    int g = asy[i];
    int src = iw[g >> 6] * 64 + (g & 63);
    float4 v = reinterpret_cast<const float4*>(X + (size_t)src * C_DIM)[lane];
    float m = warp_sum(v.x + v.y + v.z + v.w) * (1.0f / C_DIM);
    float dx = v.x - m, dy = v.y - m, dz = v.z - m, dw = v.w - m;
    float var = warp_sum(dx*dx + dy*dy + dz*dz + dw*dw) * (1.0f / C_DIM);
    float inv = rsqrtf(var + EPS_LN);
    float4 wv = reinterpret_cast<const float4*>(w)[lane];
    float4 bv = reinterpret_cast<const float4*>(b)[lane];
    float4 r;
    r.x = dx * inv * wv.x + bv.x;
    r.y = dy * inv * wv.y + bv.y;
    r.z = dz * inv * wv.z + bv.z;
    r.w = dw * inv * wv.w + bv.w;
    reinterpret_cast<float4*>(g_xa + (size_t)i * C_DIM)[lane] = r;
}

// ---------------------------------------------------------------------------
// K5: fused per-partition attention. One block per partition m (4096 blocks).
//   gather 64x128 inputs -> QKV (64x384) -> 4 heads of 64x64 attention with
//   blocked-key mask -> O (64x128) -> proj -> scatter outputs.
// ---------------------------------------------------------------------------
#define XS 132      // xp / o row stride (padded)
#define QS 385      // qkv row stride (padded)
#define SS 66       // scores row stride (padded)
#define WS 388      // weight stage row stride (padded)
#define ATTN_SMEM_BYTES ((8448 + 24640 + 4224 + 6208 + 192) * 4)

__global__ void __launch_bounds__(256, 1) attn_kernel(
    const float* __restrict__ X,
    const int* __restrict__ ipart, const int* __restrict__ iw,
    const float* __restrict__ qkvw, const float* __restrict__ qkvb,
    const float* __restrict__ projw, const float* __restrict__ projb,
    float* __restrict__ out)
{
    extern __shared__ float sm[];
    float* xsm = sm;                  // 64 x XS  (xp, later reused for O)
    float* qsm = sm + 8448;           // 64 x QS
    float* ssm = qsm + 24640;         // 64 x SS
    float* ws  = ssm + 4224;          // 16 x WS
    int* kfl   = (int*)(ws + 6208);   // 64
    int* orow  = kfl + 64;            // 64
    int* rnk   = orow + 64;           // 64

    int m   = blockIdx.x;
    int tid = threadIdx.x;
    int tx  = tid & 15;
    int ty  = tid >> 4;

    // per-partition metadata
    if (tid < 64) {
        int g = ipart[m * 64 + tid];
        int f = g_flag[g];
        kfl[tid]  = f;
        orow[tid] = iw[g >> 6] * 64 + (g & 63);
        rnk[tid]  = (f == 1) ? g_rank[g] : 0;
    }
    __syncthreads();

    // gather xp (asy rows come from g_xa, others from X)
    for (int idx = tid; idx < 64 * 128; idx += 256) {
        int j = idx >> 7, c = idx & 127;
        const float* src = (kfl[j] == 1) ? (g_xa + (size_t)rnk[j] * C_DIM)
                                         : (X + (size_t)orow[j] * C_DIM);
        xsm[j * XS + c] = src[c];
    }
    __syncthreads();

    // ---- QKV: (64x128) @ (128x384) + bias ----
    float acc[4][24];
#pragma unroll
    for (int j = 0; j < 24; j++) {
        float bv = __ldg(&qkvb[tx + 16 * j]);
#pragma unroll
        for (int i = 0; i < 4; i++) acc[i][j] = bv;
    }
    for (int kk = 0; kk < 8; kk++) {
        for (int idx = tid; idx < 16 * 384; idx += 256) {
            int r = idx / 384, c = idx - r * 384;
            ws[r * WS + c] = qkvw[(kk * 16 + r) * 384 + c];
        }
        __syncthreads();
#pragma unroll
        for (int k = 0; k < 16; k++) {
            float xv[4];
#pragma unroll
            for (int i = 0; i < 4; i++) xv[i] = xsm[(ty + 16 * i) * XS + kk * 16 + k];
#pragma unroll
            for (int j = 0; j < 24; j++) {
                float wv = ws[k * WS + tx + 16 * j];
#pragma unroll
                for (int i = 0; i < 4; i++) acc[i][j] += xv[i] * wv;
            }
        }
        __syncthreads();
    }
#pragma unroll
    for (int i = 0; i < 4; i++)
#pragma unroll
        for (int j = 0; j < 24; j++)
            qsm[(ty + 16 * i) * QS + tx + 16 * j] = acc[i][j];
    __syncthreads();

    // ---- attention per head ----
    const float scale = 0.17677669529663687f;   // 32^-0.5
    int warp = tid >> 5, lane = tid & 31;
    for (int h = 0; h < 4; h++) {
        int bq = h * 96, bk = h * 96 + 32, bv = h * 96 + 64;
        float sacc[4][4];
#pragma unroll
        for (int i = 0; i < 4; i++)
#pragma unroll
            for (int j = 0; j < 4; j++) sacc[i][j] = 0.0f;
#pragma unroll
        for (int d = 0; d < 32; d++) {
            float qv[4], kv[4];
#pragma unroll
            for (int i = 0; i < 4; i++) qv[i] = qsm[(ty + 16 * i) * QS + bq + d];
#pragma unroll
            for (int j = 0; j < 4; j++) kv[j] = qsm[(tx + 16 * j) * QS + bk + d];
#pragma unroll
            for (int i = 0; i < 4; i++)
#pragma unroll
                for (int j = 0; j < 4; j++) sacc[i][j] += qv[i] * kv[j];
        }
#pragma unroll
        for (int i = 0; i < 4; i++)
#pragma unroll
            for (int j = 0; j < 4; j++) {
                int ki = tx + 16 * j;
                ssm[(ty + 16 * i) * SS + ki] =
                    (kfl[ki] == 2) ? -10000.0f : sacc[i][j] * scale;
            }
        __syncthreads();

        // softmax over keys: 8 warps x 8 rows each
        for (int q = warp; q < 64; q += 8) {
            float v0 = ssm[q * SS + lane];
            float v1 = ssm[q * SS + lane + 32];
            float mx = warp_max(fmaxf(v0, v1));
            float e0 = __expf(v0 - mx), e1 = __expf(v1 - mx);
            float s = warp_sum(e0 + e1);
            float rinv = 1.0f / s;
            ssm[q * SS + lane]      = e0 * rinv;
            ssm[q * SS + lane + 32] = e1 * rinv;
        }
        __syncthreads();

        // O_h = attn @ v  (64x32), store into xsm (xp is dead)
        float oacc[4][2];
#pragma unroll
        for (int i = 0; i < 4; i++) { oacc[i][0] = 0.0f; oacc[i][1] = 0.0f; }
        for (int ki = 0; ki < 64; ki++) {
            float pv[4];
#pragma unroll
            for (int i = 0; i < 4; i++) pv[i] = ssm[(ty + 16 * i) * SS + ki];
            float vv0 = qsm[ki * QS + bv + tx];
            float vv1 = qsm[ki * QS + bv + tx + 16];
#pragma unroll
            for (int i = 0; i < 4; i++) {
                oacc[i][0] += pv[i] * vv0;
                oacc[i][1] += pv[i] * vv1;
            }
        }
#pragma unroll
        for (int i = 0; i < 4; i++) {
            xsm[(ty + 16 * i) * XS + h * 32 + tx]      = oacc[i][0];
            xsm[(ty + 16 * i) * XS + h * 32 + tx + 16] = oacc[i][1];
        }
        __syncthreads();
    }

    // ---- proj: (64x128) @ (128x128) + bias, then scatter ----
    float pacc[4][8];
#pragma unroll
    for (int j = 0; j < 8; j++) {
        float bv = __ldg(&projb[tx + 16 * j]);
#pragma unroll
        for (int i = 0; i < 4; i++) pacc[i][j] = bv;
    }
    for (int kk = 0; kk < 8; kk++) {
        for (int idx = tid; idx < 16 * 128; idx += 256) {
            int r = idx >> 7, c = idx & 127;
            ws[r * WS + c] = projw[(kk * 16 + r) * 128 + c];
        }
        __syncthreads();
#pragma unroll
        for (int k = 0; k < 16; k++) {
            float xv[4];
#pragma unroll
            for (int i = 0; i < 4; i++) xv[i] = xsm[(ty + 16 * i) * XS + kk * 16 + k];
#pragma unroll
            for (int j = 0; j < 8; j++) {
                float wv = ws[k * WS + tx + 16 * j];
#pragma unroll
                for (int i = 0; i < 4; i++) pacc[i][j] += xv[i] * wv;
            }
        }
        __syncthreads();
    }
#pragma unroll
    for (int i = 0; i < 4; i++) {
        int r = ty + 16 * i;
        int f = kfl[r];
        if (f == 2) continue;                  // blocked: keep LN(x) already in out
        float* dst = (f == 1) ? (g_att + (size_t)rnk[r] * C_DIM)
                              : (out + (size_t)orow[r] * C_DIM);
#pragma unroll
        for (int j = 0; j < 8; j++) dst[tx + 16 * j] = pacc[i][j];
    }
}

// ---------------------------------------------------------------------------
// K6: fused MLP for asy rows. One block per 32 rows (4096 blocks).
//   y = xa + g1*att ; LN2 ; gelu(y@W1+b1)@W2+b2 ; out = y + g2*(.) ; scatter.
// ---------------------------------------------------------------------------
#define YS 132
#define HS 516
#define MLP_SMEM_BYTES ((4224 + 4224 + 16512 + 8256 + 32) * 4)

__global__ void __launch_bounds__(256, 1) mlp_kernel(
    const int* __restrict__ asy, const int* __restrict__ iw,
    const float* __restrict__ g1,
    const float* __restrict__ ln2w, const float* __restrict__ ln2b,
    const float* __restrict__ w1, const float* __restrict__ b1,
    const float* __restrict__ w2, const float* __restrict__ b2,
    const float* __restrict__ g2,
    float* __restrict__ out)
{
    extern __shared__ float sm[];
    float* ysm = sm;                  // 32 x YS  (pre-LN residual)
    float* xnm = sm + 4224;           // 32 x YS  (normalized)
    float* hsm = xnm + 4224;          // 32 x HS
    float* wst = hsm + 16512;         // max(16xHS, 32xYS)
    int* grow  = (int*)(wst + 8256);  // 32

    int tid = threadIdx.x;
    int tx  = tid & 15;
    int ty  = tid >> 4;
    int base = blockIdx.x * 32;

    if (tid < 32) {
        int g = asy[base + tid];
        grow[tid] = iw[g >> 6] * 64 + (g & 63);
    }
    for (int idx = tid; idx < 32 * 128; idx += 256) {
        int r = idx >> 7, c = idx & 127;
        size_t off = (size_t)(base + r) * C_DIM + c;
        ysm[r * YS + c] = g_xa[off] + __ldg(&g1[c]) * g_att[off];
    }
    __syncthreads();

    // LN2: 8 warps, 4 rows each
    int warp = tid >> 5, lane = tid & 31;
    for (int r = warp; r < 32; r += 8) {
        float v0 = ysm[r * YS + lane];
        float v1 = ysm[r * YS + lane + 32];
        float v2 = ysm[r * YS + lane + 64];
        float v3 = ysm[r * YS + lane + 96];
        float m = warp_sum(v0 + v1 + v2 + v3) * (1.0f / C_DIM);
        float d0 = v0 - m, d1 = v1 - m, d2 = v2 - m, d3 = v3 - m;
        float var = warp_sum(d0*d0 + d1*d1 + d2*d2 + d3*d3) * (1.0f / C_DIM);
        float inv = rsqrtf(var + EPS_LN);
        xnm[r * YS + lane]      = d0 * inv * __ldg(&ln2w[lane])      + __ldg(&ln2b[lane]);
        xnm[r * YS + lane + 32] = d1 * inv * __ldg(&ln2w[lane + 32]) + __ldg(&ln2b[lane + 32]);
        xnm[r * YS + lane + 64] = d2 * inv * __ldg(&ln2w[lane + 64]) + __ldg(&ln2b[lane + 64]);
        xnm[r * YS + lane + 96] = d3 * inv * __ldg(&ln2w[lane + 96]) + __ldg(&ln2b[lane + 96]);
    }
    __syncthreads();

    // GEMM1 (32x128)@(128x512) + b1, exact gelu
    float acc[2][32];
#pragma unroll
    for (int j = 0; j < 32; j++) {
        float bv = __ldg(&b1[tx + 16 * j]);
        acc[0][j] = bv; acc[1][j] = bv;
    }
    for (int kk = 0; kk < 8; kk++) {
        for (int idx = tid; idx < 16 * 512; idx += 256) {
            int r = idx >> 9, c = idx & 511;
            wst[r * HS + c] = w1[(kk * 16 + r) * 512 + c];
        }
        __syncthreads();
#pragma unroll
        for (int k = 0; k < 16; k++) {
            float x0 = xnm[ty * YS + kk * 16 + k];
            float x1 = xnm[(ty + 16) * YS + kk * 16 + k];
#pragma unroll
            for (int j = 0; j < 32; j++) {
                float wv = wst[k * HS + tx + 16 * j];
                acc[0][j] += x0 * wv;
                acc[1][j] += x1 * wv;
            }
        }
        __syncthreads();
    }
#pragma unroll
    for (int i = 0; i < 2; i++)
#pragma unroll
        for (int j = 0; j < 32; j++) {
            float v = acc[i][j];
            float ge = 0.5f * v * (1.0f + erff(v * 0.7071067811865476f));
            hsm[(ty + 16 * i) * HS + tx + 16 * j] = ge;
        }
    __syncthreads();

    // GEMM2 (32x512)@(512x128) + b2
    float a2[2][8];
#pragma unroll
    for (int j = 0; j < 8; j++) {
        float bv = __ldg(&b2[tx + 16 * j]);
        a2[0][j] = bv; a2[1][j] = bv;
    }
    for (int kk = 0; kk < 16; kk++) {
        for (int idx = tid; idx < 32 * 128; idx += 256) {
            int r = idx >> 7, c = idx & 127;
            wst[r * YS + c] = w2[(kk * 32 + r) * 128 + c];
        }
        __syncthreads();
#pragma unroll
        for (int k = 0; k < 32; k++) {
            float h0 = hsm[ty * HS + kk * 32 + k];
            float h1 = hsm[(ty + 16) * HS + kk * 32 + k];
#pragma unroll
            for (int j = 0; j < 8; j++) {
                float wv = wst[k * YS + tx + 16 * j];
                a2[0][j] += h0 * wv;
                a2[1][j] += h1 * wv;
            }
        }
        __syncthreads();
    }

    // final residual + scatter
#pragma unroll
    for (int i = 0; i < 2; i++) {
        int r = ty + 16 * i;
#pragma unroll
        for (int j = 0; j < 8; j++) {
            int c = tx + 16 * j;
            float val = ysm[r * YS + c] + __ldg(&g2[c]) * a2[i][j];
            out[(size_t)grow[r] * C_DIM + c] = val;
        }
    }
}

// ---------------------------------------------------------------------------
extern "C" void kernel_launch(void* const* d_in, const int* in_sizes, int n_in,
                              void* d_out, int out_size)
{
    // input layout per metadata order; M,B scalars may or may not be present
    int base = 7;
    if (n_in == 19) base = 5;

    const float* x      = (const float*)d_in[0];
    const int*   iw     = (const int*)d_in[1];
    const int*   ipart  = (const int*)d_in[2];
    const int*   asy    = (const int*)d_in[3];
    const int*   blk    = (const int*)d_in[4];
    const float* ln1w   = (const float*)d_in[base + 0];
    const float* ln1b   = (const float*)d_in[base + 1];
    const float* qkvw   = (const float*)d_in[base + 2];
    const float* qkvb   = (const float*)d_in[base + 3];
    const float* projw  = (const float*)d_in[base + 4];
    const float* projb  = (const float*)d_in[base + 5];
    const float* g1     = (const float*)d_in[base + 6];
    const float* ln2w   = (const float*)d_in[base + 7];
    const float* ln2b   = (const float*)d_in[base + 8];
    const float* w1     = (const float*)d_in[base + 9];
    const float* b1     = (const float*)d_in[base + 10];
    const float* w2     = (const float*)d_in[base + 11];
    const float* b2     = (const float*)d_in[base + 12];
    const float* g2     = (const float*)d_in[base + 13];
    float* out = (float*)d_out;

    cudaFuncSetAttribute(attn_kernel, cudaFuncAttributeMaxDynamicSharedMemorySize,
                         ATTN_SMEM_BYTES);
    cudaFuncSetAttribute(mlp_kernel, cudaFuncAttributeMaxDynamicSharedMemorySize,
                         MLP_SMEM_BYTES);

    // 1. X = LN(x) everywhere
    ln_kernel<<<N_TOK / 8, 256>>>(x, ln1w, ln1b, out);
    // 2-3. flag/rank maps
    zero_flags_kernel<<<(MW_CNT / 16 + 255) / 256, 256>>>();
    set_flags_kernel<<<(A_CNT + BL_CNT + 255) / 256, 256>>>(asy, blk);
    // 4. xa double-LN
    xa_kernel<<<A_CNT / 8, 256>>>(out, asy, iw, ln1w, ln1b);
    // 5. fused windowed attention (one block per partition)
    attn_kernel<<<M_PART, 256, ATTN_SMEM_BYTES>>>(out, ipart, iw,
                                                  qkvw, qkvb, projw, projb, out);
    // 6. fused MLP for asy rows
    mlp_kernel<<<A_CNT / 32, 256, MLP_SMEM_BYTES>>>(asy, iw, g1, ln2w, ln2b,
                                                    w1, b1, w2, b2, g2, out);
}

// round 3
// speedup vs baseline: 2.3037x; 2.3037x over previous
#include <cuda_runtime.h>
#include <math.h>
#include <stdint.h>

// Problem constants
#define N_TOK   524288
#define P_TOK   64
#define C_DIM   128
#define M_PART  4096
#define MW_CNT  262144
#define A_CNT   131072
#define BL_CNT  65536
#define EPS_LN  1e-6f

// ---------------------------------------------------------------------------
// Scratch (device globals — allocation-free rule)
// ---------------------------------------------------------------------------
__device__ float g_xa[(size_t)A_CNT * C_DIM];        // double-LN asy rows (rank order)
__device__ float g_att[(size_t)A_CNT * C_DIM];       // proj output for asy rows (rank order)
__device__ float g_xp[(size_t)MW_CNT * C_DIM];       // gathered attention input (partition order)
__device__ float g_qkv[(size_t)MW_CNT * 384];        // QKV GEMM output
__device__ float g_o[(size_t)MW_CNT * C_DIM];        // attention output (pre-proj)
__device__ float g_y[(size_t)A_CNT * C_DIM];         // MLP residual input
__device__ float g_yn[(size_t)A_CNT * C_DIM];        // LN2(y)
__device__ float g_h[(size_t)A_CNT * 512];           // MLP hidden (post-gelu)
__device__ unsigned char g_flag[MW_CNT];             // 0 none, 1 asy, 2 blocked
__device__ int g_rank[MW_CNT];
__device__ int g_asyrow[A_CNT];                      // window row of asy[i]
__device__ unsigned char g_mflag[MW_CNT];            // partition-order meta
__device__ int g_mrow[MW_CNT];
__device__ int g_mrank[MW_CNT];

// ---------------------------------------------------------------------------
// helpers
// ---------------------------------------------------------------------------
__device__ __forceinline__ float warp_sum(float v) {
#pragma unroll
    for (int o = 16; o; o >>= 1) v += __shfl_xor_sync(0xffffffffu, v, o);
    return v;
}
__device__ __forceinline__ float warp_max(float v) {
#pragma unroll
    for (int o = 16; o; o >>= 1) v = fmaxf(v, __shfl_xor_sync(0xffffffffu, v, o));
    return v;
}
__device__ __forceinline__ uint32_t f2tf32(float f) {
    uint32_t r;
    asm("cvt.rna.tf32.f32 %0, %1;" : "=r"(r) : "f"(f));
    return r;
}
__device__ __forceinline__ void mma_tf32(float c[4], const uint32_t a[4], const uint32_t b[2]) {
    asm volatile(
        "mma.sync.aligned.m16n8k8.row.col.f32.tf32.tf32.f32 "
        "{%0,%1,%2,%3}, {%4,%5,%6,%7}, {%8,%9}, {%0,%1,%2,%3};"
        : "+f"(c[0]), "+f"(c[1]), "+f"(c[2]), "+f"(c[3])
        : "r"(a[0]), "r"(a[1]), "r"(a[2]), "r"(a[3]), "r"(b[0]), "r"(b[1]));
}

// ---------------------------------------------------------------------------
// K1: X = LN(x) for all rows -> d_out
// ---------------------------------------------------------------------------
__global__ void __launch_bounds__(256) ln_kernel(
    const float* __restrict__ x, const float* __restrict__ w,
    const float* __restrict__ b, float* __restrict__ out)
{
    int row  = (int)((blockIdx.x * 256u + threadIdx.x) >> 5);
    int lane = threadIdx.x & 31;
    if (row >= N_TOK) return;
    float4 v = reinterpret_cast<const float4*>(x + (size_t)row * C_DIM)[lane];
    float m = warp_sum(v.x + v.y + v.z + v.w) * (1.0f / C_DIM);
    float dx = v.x - m, dy = v.y - m, dz = v.z - m, dw = v.w - m;
    float var = warp_sum(dx*dx + dy*dy + dz*dz + dw*dw) * (1.0f / C_DIM);
    float inv = rsqrtf(var + EPS_LN);
    float4 wv = reinterpret_cast<const float4*>(w)[lane];
    float4 bv = reinterpret_cast<const float4*>(b)[lane];
    float4 r;
    r.x = dx * inv * wv.x + bv.x; r.y = dy * inv * wv.y + bv.y;
    r.z = dz * inv * wv.z + bv.z; r.w = dw * inv * wv.w + bv.w;
    reinterpret_cast<float4*>(out + (size_t)row * C_DIM)[lane] = r;
}

// ---------------------------------------------------------------------------
// K2/K3: flag + rank maps
// ---------------------------------------------------------------------------
__global__ void __launch_bounds__(256) zero_flags_kernel()
{
    int t = blockIdx.x * 256 + threadIdx.x;
    if (t < MW_CNT / 16)
        reinterpret_cast<uint4*>(g_flag)[t] = make_uint4(0u, 0u, 0u, 0u);
}
__global__ void __launch_bounds__(256) set_flags_kernel(
    const int* __restrict__ asy, const int* __restrict__ blk, const int* __restrict__ iw)
{
    int t = blockIdx.x * 256 + threadIdx.x;
    if (t < A_CNT) {
        int g = asy[t];
        g_flag[g] = 1;
        g_rank[g] = t;
        g_asyrow[t] = iw[g >> 6] * 64 + (g & 63);
    } else if (t < A_CNT + BL_CNT) {
        g_flag[blk[t - A_CNT]] = 2;
    }
}

// ---------------------------------------------------------------------------
// K4: xa = LN(X[window row of asy[i]]) -> g_xa
// ---------------------------------------------------------------------------
__global__ void __launch_bounds__(256) xa_kernel(
    const float* __restrict__ X, const int* __restrict__ asy,
    const int* __restrict__ iw,
    const float* __restrict__ w, const float* __restrict__ b)
{
    int i    = (int)((blockIdx.x * 256u + threadIdx.x) >> 5);
    int lane = threadIdx.x & 31;
    if (i >= A_CNT) return;
    int g = asy[i];
    int src = iw[g >> 6] * 64 + (g & 63);
    float4 v = reinterpret_cast<const float4*>(X + (size_t)src * C_DIM)[lane];
    float m = warp_sum(v.x + v.y + v.z + v.w) * (1.0f / C_DIM);
    float dx = v.x - m, dy = v.y - m, dz = v.z - m, dw = v.w - m;
    float var = warp_sum(dx*dx + dy*dy + dz*dz + dw*dw) * (1.0f / C_DIM);
    float inv = rsqrtf(var + EPS_LN);
    float4 wv = reinterpret_cast<const float4*>(w)[lane];
    float4 bv = reinterpret_cast<const float4*>(b)[lane];
    float4 r;
    r.x = dx * inv * wv.x + bv.x; r.y = dy * inv * wv.y + bv.y;
    r.z = dz * inv * wv.z + bv.z; r.w = dw * inv * wv.w + bv.w;
    reinterpret_cast<float4*>(g_xa + (size_t)i * C_DIM)[lane] = r;
}

// ---------------------------------------------------------------------------
// K5: gather partition-order rows into g_xp + meta arrays
// ---------------------------------------------------------------------------
__global__ void __launch_bounds__(256) gather_kernel(
    const float* __restrict__ X, const int* __restrict__ ipart, const int* __restrict__ iw)
{
    int i    = (int)((blockIdx.x * 256u + threadIdx.x) >> 5);
    int lane = threadIdx.x & 31;
    if (i >= MW_CNT) return;
    int g = ipart[i];
    int f = g_flag[g];
    int wrow = iw[g >> 6] * 64 + (g & 63);
    int rnk = (f == 1) ? g_rank[g] : 0;
    if (lane == 0) { g_mflag[i] = (unsigned char)f; g_mrow[i] = wrow; g_mrank[i] = rnk; }
    const float* srcp = (f == 1) ? (g_xa + (size_t)rnk * C_DIM)
                                 : (X + (size_t)wrow * C_DIM);
    float4 v = reinterpret_cast<const float4*>(srcp)[lane];
    reinterpret_cast<float4*>(g_xp + (size_t)i * C_DIM)[lane] = v;
}

// ---------------------------------------------------------------------------
// tf32 warp-MMA GEMM:  C[Mtot x NTOT] = A[Mtot x KTOT] @ W[KTOT x NTOT]
//   block tile 128 x 64 (grid.y covers NTOT/64), 8 warps 4x2, warp tile 32x32
//   EPI 0: + bias -> out                               [QKV]
//   EPI 1: + bias, scatter via g_m* meta               [proj]
//   EPI 2: + bias, gelu -> out                         [MLP1]
//   EPI 3: + bias, g_y + evec*acc -> out[g_asyrow]     [MLP2]
// ---------------------------------------------------------------------------
#define AS_STRIDE 36
#define BS_STRIDE 72

template<int NTOT, int KTOT, int EPI>
__global__ void __launch_bounds__(256) gemm_mma_kernel(
    const float* __restrict__ A, const float* __restrict__ W,
    const float* __restrict__ bias, float* __restrict__ out,
    const float* __restrict__ evec)
{
    __shared__ float As[128 * AS_STRIDE];
    __shared__ float Bs[32 * BS_STRIDE];

    int tid  = threadIdx.x;
    int lane = tid & 31;
    int wid  = tid >> 5;
    int wr   = wid >> 1;          // 0..3
    int wc   = wid & 1;           // 0..1
    int g    = lane >> 2;         // 0..7
    int tg   = lane & 3;          // 0..3
    size_t m0 = (size_t)blockIdx.x * 128;
    int n0 = blockIdx.y * 64;

    float c[2][4][4];
#pragma unroll
    for (int i = 0; i < 2; i++)
#pragma unroll
        for (int j = 0; j < 4; j++)
#pragma unroll
            for (int q = 0; q < 4; q++) c[i][j][q] = 0.0f;

    for (int kc = 0; kc < KTOT / 32; kc++) {
        // stage A chunk: 128 x 32, tf32-rounded
#pragma unroll
        for (int t = 0; t < 4; t++) {
            int i4 = tid + t * 256;
            int r = i4 >> 3, cc = (i4 & 7) * 4;
            float4 v = *reinterpret_cast<const float4*>(
                A + (m0 + r) * KTOT + kc * 32 + cc);
            uint4 u;
            u.x = f2tf32(v.x); u.y = f2tf32(v.y); u.z = f2tf32(v.z); u.w = f2tf32(v.w);
            *reinterpret_cast<uint4*>(&As[r * AS_STRIDE + cc]) = u;
        }
        // stage B chunk: 32 x 64 of W[k][n]
#pragma unroll
        for (int t = 0; t < 2; t++) {
            int i4 = tid + t * 256;
            int r = i4 >> 4, cc = (i4 & 15) * 4;
            float4 v = *reinterpret_cast<const float4*>(
                W + (size_t)(kc * 32 + r) * NTOT + n0 + cc);
            uint4 u;
            u.x = f2tf32(v.x); u.y = f2tf32(v.y); u.z = f2tf32(v.z); u.w = f2tf32(v.w);
            *reinterpret_cast<uint4*>(&Bs[r * BS_STRIDE + cc]) = u;
        }
        __syncthreads();

#pragma unroll
        for (int kb = 0; kb < 4; kb++) {
            uint32_t a[2][4], b[4][2];
#pragma unroll
            for (int i = 0; i < 2; i++) {
                int row = wr * 32 + i * 16 + g;
                a[i][0] = __float_as_uint(As[row * AS_STRIDE + kb * 8 + tg]);
                a[i][1] = __float_as_uint(As[(row + 8) * AS_STRIDE + kb * 8 + tg]);
                a[i][2] = __float_as_uint(As[row * AS_STRIDE + kb * 8 + tg + 4]);
                a[i][3] = __float_as_uint(As[(row + 8) * AS_STRIDE + kb * 8 + tg + 4]);
            }
#pragma unroll
            for (int j = 0; j < 4; j++) {
                int n = wc * 32 + j * 8 + g;
                b[j][0] = __float_as_uint(Bs[(kb * 8 + tg) * BS_STRIDE + n]);
                b[j][1] = __float_as_uint(Bs[(kb * 8 + tg + 4) * BS_STRIDE + n]);
            }
#pragma unroll
            for (int i = 0; i < 2; i++)
#pragma unroll
                for (int j = 0; j < 4; j++)
                    mma_tf32(c[i][j], a[i], b[j]);
        }
        __syncthreads();
    }

    // ---- epilogue ----
#pragma unroll
    for (int i = 0; i < 2; i++) {
        int r0 = wr * 32 + i * 16 + g;
#pragma unroll
        for (int half = 0; half < 2; half++) {
            size_t grow = m0 + r0 + half * 8;
            float* dst;
            int f = 0;
            if constexpr (EPI == 0) {
                dst = out + grow * NTOT;
            } else if constexpr (EPI == 1) {
                f = g_mflag[grow];
                dst = (f == 1) ? (g_att + (size_t)g_mrank[grow] * C_DIM)
                               : (out + (size_t)g_mrow[grow] * C_DIM);
            } else if constexpr (EPI == 2) {
                dst = out + grow * NTOT;
            } else {
                dst = out + (size_t)g_asyrow[grow] * C_DIM;
            }
#pragma unroll
            for (int j = 0; j < 4; j++) {
                int colg = n0 + wc * 32 + j * 8 + tg * 2;
                float v0 = c[i][j][half * 2]     + __ldg(&bias[colg]);
                float v1 = c[i][j][half * 2 + 1] + __ldg(&bias[colg + 1]);
                if constexpr (EPI == 2) {
                    v0 = 0.5f * v0 * (1.0f + erff(v0 * 0.7071067811865476f));
                    v1 = 0.5f * v1 * (1.0f + erff(v1 * 0.7071067811865476f));
                }
                if constexpr (EPI == 3) {
                    v0 = g_y[grow * C_DIM + colg]     + __ldg(&evec[colg]) * v0;
                    v1 = g_y[grow * C_DIM + colg + 1] + __ldg(&evec[colg + 1]) * v1;
                }
                if constexpr (EPI == 1) {
                    if (f != 2) { dst[colg] = v0; dst[colg + 1] = v1; }
                } else {
                    dst[colg] = v0; dst[colg + 1] = v1;
                }
            }
        }
    }
}

// ---------------------------------------------------------------------------
// K7: scalar attention per partition.  g_qkv (64x384) -> g_o (64x128)
// ---------------------------------------------------------------------------
#define QS 385
#define SS 66
#define ATTN2_SMEM_BYTES ((64 * QS + 64 * SS) * 4 + 256)

__global__ void __launch_bounds__(256, 1) attn2_kernel(
    const float* __restrict__ gqkv, float* __restrict__ go)
{
    extern __shared__ float sm[];
    float* qsm = sm;                  // 64 x QS
    float* ssm = sm + 64 * QS;        // 64 x SS
    int* kfl   = (int*)(ssm + 64 * SS);

    int m   = blockIdx.x;
    int tid = threadIdx.x;
    int tx  = tid & 15;
    int ty  = tid >> 4;

    if (tid < 64) kfl[tid] = g_mflag[m * 64 + tid];

    const float4* src = reinterpret_cast<const float4*>(gqkv + (size_t)m * 64 * 384);
    for (int i = tid; i < 6144; i += 256) {
        int r = i / 96, c4 = (i - r * 96) * 4;
        float4 v = src[i];
        qsm[r * QS + c4]     = v.x;
        qsm[r * QS + c4 + 1] = v.y;
        qsm[r * QS + c4 + 2] = v.z;
        qsm[r * QS + c4 + 3] = v.w;
    }
    __syncthreads();

    const float scale = 0.17677669529663687f;
    int warp = tid >> 5, lane = tid & 31;
    for (int h = 0; h < 4; h++) {
        int bq = h * 96, bk = h * 96 + 32, bv = h * 96 + 64;
        float sacc[4][4];
#pragma unroll
        for (int i = 0; i < 4; i++)
#pragma unroll
            for (int j = 0; j < 4; j++) sacc[i][j] = 0.0f;
#pragma unroll
        for (int d = 0; d < 32; d++) {
            float qv[4], kv[4];
#pragma unroll
            for (int i = 0; i < 4; i++) qv[i] = qsm[(ty + 16 * i) * QS + bq + d];
#pragma unroll
            for (int j = 0; j < 4; j++) kv[j] = qsm[(tx + 16 * j) * QS + bk + d];
#pragma unroll
            for (int i = 0; i < 4; i++)
#pragma unroll
                for (int j = 0; j < 4; j++) sacc[i][j] += qv[i] * kv[j];
        }
#pragma unroll
        for (int i = 0; i < 4; i++)
#pragma unroll
            for (int j = 0; j < 4; j++) {
                int ki = tx + 16 * j;
                ssm[(ty + 16 * i) * SS + ki] =
                    (kfl[ki] == 2) ? -10000.0f : sacc[i][j] * scale;
            }
        __syncthreads();

        for (int q = warp; q < 64; q += 8) {
            float v0 = ssm[q * SS + lane];
            float v1 = ssm[q * SS + lane + 32];
            float mx = warp_max(fmaxf(v0, v1));
            float e0 = __expf(v0 - mx), e1 = __expf(v1 - mx);
            float s = warp_sum(e0 + e1);
            float rinv = 1.0f / s;
            ssm[q * SS + lane]      = e0 * rinv;
            ssm[q * SS + lane + 32] = e1 * rinv;
        }
        __syncthreads();

        float oacc[4][2];
#pragma unroll
        for (int i = 0; i < 4; i++) { oacc[i][0] = 0.0f; oacc[i][1] = 0.0f; }
        for (int ki = 0; ki < 64; ki++) {
            float pv[4];
#pragma unroll
            for (int i = 0; i < 4; i++) pv[i] = ssm[(ty + 16 * i) * SS + ki];
            float vv0 = qsm[ki * QS + bv + tx];
            float vv1 = qsm[ki * QS + bv + tx + 16];
#pragma unroll
            for (int i = 0; i < 4; i++) {
                oacc[i][0] += pv[i] * vv0;
                oacc[i][1] += pv[i] * vv1;
            }
        }
#pragma unroll
        for (int i = 0; i < 4; i++) {
            size_t orow = (size_t)(m * 64 + ty + 16 * i) * C_DIM;
            go[orow + h * 32 + tx]      = oacc[i][0];
            go[orow + h * 32 + tx + 16] = oacc[i][1];
        }
        __syncthreads();
    }
}

// ---------------------------------------------------------------------------
// K8: y = xa + g1*att -> g_y ; g_yn = LN2(y).  One warp per row.
// ---------------------------------------------------------------------------
__global__ void __launch_bounds__(256) ybuild_kernel(
    const float* __restrict__ g1,
    const float* __restrict__ ln2w, const float* __restrict__ ln2b)
{
    int r    = (int)((blockIdx.x * 256u + threadIdx.x) >> 5);
    int lane = threadIdx.x & 31;
    if (r >= A_CNT) return;
    float4 a = reinterpret_cast<const float4*>(g_xa + (size_t)r * C_DIM)[lane];
    float4 t = reinterpret_cast<const float4*>(g_att + (size_t)r * C_DIM)[lane];
    float4 gv = reinterpret_cast<const float4*>(g1)[lane];
    float4 y;
    y.x = a.x + gv.x * t.x; y.y = a.y + gv.y * t.y;
    y.z = a.z + gv.z * t.z; y.w = a.w + gv.w * t.w;
    reinterpret_cast<float4*>(g_y + (size_t)r * C_DIM)[lane] = y;
    float m = warp_sum(y.x + y.y + y.z + y.w) * (1.0f / C_DIM);
    float dx = y.x - m, dy = y.y - m, dz = y.z - m, dw = y.w - m;
    float var = warp_sum(dx*dx + dy*dy + dz*dz + dw*dw) * (1.0f / C_DIM);
    float inv = rsqrtf(var + EPS_LN);
    float4 wv = reinterpret_cast<const float4*>(ln2w)[lane];
    float4 bv = reinterpret_cast<const float4*>(ln2b)[lane];
    float4 o;
    o.x = dx * inv * wv.x + bv.x; o.y = dy * inv * wv.y + bv.y;
    o.z = dz * inv * wv.z + bv.z; o.w = dw * inv * wv.w + bv.w;
    reinterpret_cast<float4*>(g_yn + (size_t)r * C_DIM)[lane] = o;
}

// ---------------------------------------------------------------------------
extern "C" void kernel_launch(void* const* d_in, const int* in_sizes, int n_in,
                              void* d_out, int out_size)
{
    int base = 7;
    if (n_in == 19) base = 5;

    const float* x      = (const float*)d_in[0];
    const int*   iw     = (const int*)d_in[1];
    const int*   ipart  = (const int*)d_in[2];
    const int*   asy    = (const int*)d_in[3];
    const int*   blk    = (const int*)d_in[4];
    const float* ln1w   = (const float*)d_in[base + 0];
    const float* ln1b   = (const float*)d_in[base + 1];
    const float* qkvw   = (const float*)d_in[base + 2];
    const float* qkvb   = (const float*)d_in[base + 3];
    const float* projw  = (const float*)d_in[base + 4];
    const float* projb  = (const float*)d_in[base + 5];
    const float* g1     = (const float*)d_in[base + 6];
    const float* ln2w   = (const float*)d_in[base + 7];
    const float* ln2b   = (const float*)d_in[base + 8];
    const float* w1     = (const float*)d_in[base + 9];
    const float* b1     = (const float*)d_in[base + 10];
    const float* w2     = (const float*)d_in[base + 11];
    const float* b2     = (const float*)d_in[base + 12];
    const float* g2     = (const float*)d_in[base + 13];
    float* out = (float*)d_out;

    float *p_xp, *p_qkv, *p_o, *p_yn, *p_h;
    cudaGetSymbolAddress((void**)&p_xp, g_xp);
    cudaGetSymbolAddress((void**)&p_qkv, g_qkv);
    cudaGetSymbolAddress((void**)&p_o, g_o);
    cudaGetSymbolAddress((void**)&p_yn, g_yn);
    cudaGetSymbolAddress((void**)&p_h, g_h);

    cudaFuncSetAttribute(attn2_kernel,
                         cudaFuncAttributeMaxDynamicSharedMemorySize, ATTN2_SMEM_BYTES);

    // 1. X = LN(x)
    ln_kernel<<<N_TOK / 8, 256>>>(x, ln1w, ln1b, out);
    // 2-3. flag/rank maps
    zero_flags_kernel<<<(MW_CNT / 16 + 255) / 256, 256>>>();
    set_flags_kernel<<<(A_CNT + BL_CNT + 255) / 256, 256>>>(asy, blk, iw);
    // 4. xa double-LN
    xa_kernel<<<A_CNT / 8, 256>>>(out, asy, iw, ln1w, ln1b);
    // 5. gather attention input + meta
    gather_kernel<<<MW_CNT / 8, 256>>>(out, ipart, iw);
    // 6. QKV GEMM (tensor cores, tf32 mma.sync)
    gemm_mma_kernel<384, 128, 0><<<dim3(MW_CNT / 128, 6), 256>>>(
        p_xp, qkvw, qkvb, p_qkv, nullptr);
    // 7. attention (scalar)
    attn2_kernel<<<M_PART, 256, ATTN2_SMEM_BYTES>>>(p_qkv, p_o);
    // 8. proj GEMM + scatter
    gemm_mma_kernel<128, 128, 1><<<dim3(MW_CNT / 128, 2), 256>>>(
        p_o, projw, projb, out, nullptr);
    // 9. y build + LN2
    ybuild_kernel<<<A_CNT / 8, 256>>>(g1, ln2w, ln2b);
    // 10. MLP GEMM1 + gelu
    gemm_mma_kernel<512, 128, 2><<<dim3(A_CNT / 128, 8), 256>>>(
        p_yn, w1, b1, p_h, nullptr);
    // 11. MLP GEMM2 + residual + scatter
    gemm_mma_kernel<128, 512, 3><<<dim3(A_CNT / 128, 2), 256>>>(
        p_h, w2, b2, out, g2);
}

// round 4
// speedup vs baseline: 4.1278x; 1.7918x over previous
#include <cuda_runtime.h>
#include <math.h>
#include <stdint.h>

// Problem constants
#define N_TOK   524288
#define P_TOK   64
#define C_DIM   128
#define M_PART  4096
#define MW_CNT  262144
#define A_CNT   131072
#define BL_CNT  65536
#define EPS_LN  1e-6f

// ---------------------------------------------------------------------------
// Scratch (device globals — allocation-free rule)
// ---------------------------------------------------------------------------
__device__ float g_xa[(size_t)A_CNT * C_DIM];        // double-LN asy rows (rank order)
__device__ float g_att[(size_t)A_CNT * C_DIM];       // proj output for asy rows (rank order)
__device__ float g_xp[(size_t)MW_CNT * C_DIM];       // gathered attention input (partition order)
__device__ float g_qkv[(size_t)MW_CNT * 384];        // QKV GEMM output
__device__ float g_o[(size_t)MW_CNT * C_DIM];        // attention output (pre-proj)
__device__ float g_y[(size_t)A_CNT * C_DIM];         // MLP residual input
__device__ float g_yn[(size_t)A_CNT * C_DIM];        // LN2(y)
__device__ float g_h[(size_t)A_CNT * 512];           // MLP hidden (post-gelu)
__device__ unsigned char g_flag[MW_CNT];             // 0 none, 1 asy, 2 blocked
__device__ int g_rank[MW_CNT];
__device__ int g_asyrow[A_CNT];                      // window row of asy[i]
__device__ unsigned char g_mflag[MW_CNT];            // partition-order meta
__device__ int g_mrow[MW_CNT];
__device__ int g_mrank[MW_CNT];

// ---------------------------------------------------------------------------
// helpers
// ---------------------------------------------------------------------------
__device__ __forceinline__ float warp_sum(float v) {
#pragma unroll
    for (int o = 16; o; o >>= 1) v += __shfl_xor_sync(0xffffffffu, v, o);
    return v;
}
__device__ __forceinline__ void mma_tf32(float c[4], const uint32_t a[4], const uint32_t b[2]) {
    asm volatile(
        "mma.sync.aligned.m16n8k8.row.col.f32.tf32.tf32.f32 "
        "{%0,%1,%2,%3}, {%4,%5,%6,%7}, {%8,%9}, {%0,%1,%2,%3};"
        : "+f"(c[0]), "+f"(c[1]), "+f"(c[2]), "+f"(c[3])
        : "r"(a[0]), "r"(a[1]), "r"(a[2]), "r"(a[3]), "r"(b[0]), "r"(b[1]));
}
__device__ __forceinline__ uint32_t smem_u32(const void* p) {
    uint32_t a;
    asm("{ .reg .u64 t; cvta.to.shared.u64 t, %1; cvt.u32.u64 %0, t; }" : "=r"(a) : "l"(p));
    return a;
}
__device__ __forceinline__ void cp_async16(uint32_t dst, const void* src) {
    asm volatile("cp.async.cg.shared.global [%0], [%1], 16;" :: "r"(dst), "l"(src) : "memory");
}

// ---------------------------------------------------------------------------
// K1: X = LN(x) for all rows -> d_out
// ---------------------------------------------------------------------------
__global__ void __launch_bounds__(256) ln_kernel(
    const float* __restrict__ x, const float* __restrict__ w,
    const float* __restrict__ b, float* __restrict__ out)
{
    int row  = (int)((blockIdx.x * 256u + threadIdx.x) >> 5);
    int lane = threadIdx.x & 31;
    if (row >= N_TOK) return;
    float4 v = reinterpret_cast<const float4*>(x + (size_t)row * C_DIM)[lane];
    float m = warp_sum(v.x + v.y + v.z + v.w) * (1.0f / C_DIM);
    float dx = v.x - m, dy = v.y - m, dz = v.z - m, dw = v.w - m;
    float var = warp_sum(dx*dx + dy*dy + dz*dz + dw*dw) * (1.0f / C_DIM);
    float inv = rsqrtf(var + EPS_LN);
    float4 wv = reinterpret_cast<const float4*>(w)[lane];
    float4 bv = reinterpret_cast<const float4*>(b)[lane];
    float4 r;
    r.x = dx * inv * wv.x + bv.x; r.y = dy * inv * wv.y + bv.y;
    r.z = dz * inv * wv.z + bv.z; r.w = dw * inv * wv.w + bv.w;
    reinterpret_cast<float4*>(out + (size_t)row * C_DIM)[lane] = r;
}

// ---------------------------------------------------------------------------
// K2/K3: flag + rank maps
// ---------------------------------------------------------------------------
__global__ void __launch_bounds__(256) zero_flags_kernel()
{
    int t = blockIdx.x * 256 + threadIdx.x;
    if (t < MW_CNT / 16)
        reinterpret_cast<uint4*>(g_flag)[t] = make_uint4(0u, 0u, 0u, 0u);
}
__global__ void __launch_bounds__(256) set_flags_kernel(
    const int* __restrict__ asy, const int* __restrict__ blk, const int* __restrict__ iw)
{
    int t = blockIdx.x * 256 + threadIdx.x;
    if (t < A_CNT) {
        int g = asy[t];
        g_flag[g] = 1;
        g_rank[g] = t;
        g_asyrow[t] = iw[g >> 6] * 64 + (g & 63);
    } else if (t < A_CNT + BL_CNT) {
        g_flag[blk[t - A_CNT]] = 2;
    }
}

// ---------------------------------------------------------------------------
// K4: xa = LN(X[window row of asy[i]]) -> g_xa
// ---------------------------------------------------------------------------
__global__ void __launch_bounds__(256) xa_kernel(
    const float* __restrict__ X, const int* __restrict__ asy,
    const int* __restrict__ iw,
    const float* __restrict__ w, const float* __restrict__ b)
{
    int i    = (int)((blockIdx.x * 256u + threadIdx.x) >> 5);
    int lane = threadIdx.x & 31;
    if (i >= A_CNT) return;
    int g = asy[i];
    int src = iw[g >> 6] * 64 + (g & 63);
    float4 v = reinterpret_cast<const float4*>(X + (size_t)src * C_DIM)[lane];
    float m = warp_sum(v.x + v.y + v.z + v.w) * (1.0f / C_DIM);
    float dx = v.x - m, dy = v.y - m, dz = v.z - m, dw = v.w - m;
    float var = warp_sum(dx*dx + dy*dy + dz*dz + dw*dw) * (1.0f / C_DIM);
    float inv = rsqrtf(var + EPS_LN);
    float4 wv = reinterpret_cast<const float4*>(w)[lane];
    float4 bv = reinterpret_cast<const float4*>(b)[lane];
    float4 r;
    r.x = dx * inv * wv.x + bv.x; r.y = dy * inv * wv.y + bv.y;
    r.z = dz * inv * wv.z + bv.z; r.w = dw * inv * wv.w + bv.w;
    reinterpret_cast<float4*>(g_xa + (size_t)i * C_DIM)[lane] = r;
}

// ---------------------------------------------------------------------------
// K5: gather partition-order rows into g_xp + meta arrays
// ---------------------------------------------------------------------------
__global__ void __launch_bounds__(256) gather_kernel(
    const float* __restrict__ X, const int* __restrict__ ipart, const int* __restrict__ iw)
{
    int i    = (int)((blockIdx.x * 256u + threadIdx.x) >> 5);
    int lane = threadIdx.x & 31;
    if (i >= MW_CNT) return;
    int g = ipart[i];
    int f = g_flag[g];
    int wrow = iw[g >> 6] * 64 + (g & 63);
    int rnk = (f == 1) ? g_rank[g] : 0;
    if (lane == 0) { g_mflag[i] = (unsigned char)f; g_mrow[i] = wrow; g_mrank[i] = rnk; }
    const float* srcp = (f == 1) ? (g_xa + (size_t)rnk * C_DIM)
                                 : (X + (size_t)wrow * C_DIM);
    float4 v = reinterpret_cast<const float4*>(srcp)[lane];
    reinterpret_cast<float4*>(g_xp + (size_t)i * C_DIM)[lane] = v;
}

// ---------------------------------------------------------------------------
// GEMM v2: tf32 warp-MMA, 128x128 block tile, cp.async double-buffered.
//   8 warps 4x2, warp tile 32x64 (2x8 m16n8k8 fragments).
//   EPI 0: + bias -> out                               [QKV]
//   EPI 1: + bias, scatter via g_m* meta               [proj]
//   EPI 2: + bias, gelu -> out                         [MLP1]
//   EPI 3: + bias, g_y + evec*acc -> out[g_asyrow]     [MLP2]
// ---------------------------------------------------------------------------
#define AS_STRIDE 36
#define BS_STRIDE 136
#define GEMM_ASZ (128 * AS_STRIDE)
#define GEMM_BSZ (32 * BS_STRIDE)
#define GEMM_SMEM_BYTES ((2 * GEMM_ASZ + 2 * GEMM_BSZ) * 4)

template<int NTOT, int KTOT, int EPI>
__global__ void __launch_bounds__(256) gemm2_kernel(
    const float* __restrict__ A, const float* __restrict__ W,
    const float* __restrict__ bias, float* __restrict__ out,
    const float* __restrict__ evec)
{
    extern __shared__ float smf[];
    float* As = smf;                       // 2 stages of 128x32 (stride 36)
    float* Bs = smf + 2 * GEMM_ASZ;        // 2 stages of 32x128 (stride 136)

    int tid  = threadIdx.x;
    int lane = tid & 31;
    int wid  = tid >> 5;
    int wr   = wid >> 1;          // 0..3
    int wc   = wid & 1;           // 0..1
    int g    = lane >> 2;         // 0..7
    int tg   = lane & 3;          // 0..3
    size_t m0 = (size_t)blockIdx.x * 128;
    int n0 = blockIdx.y * 128;
    constexpr int NC = KTOT / 32;

    uint32_t as_u = smem_u32(As);
    uint32_t bs_u = smem_u32(Bs);

    auto load_chunk = [&](int kc, int s) {
#pragma unroll
        for (int t = 0; t < 4; t++) {
            int idx = tid + t * 256;
            int r = idx >> 3, cc = (idx & 7) * 4;
            cp_async16(as_u + (uint32_t)(s * GEMM_ASZ + r * AS_STRIDE + cc) * 4,
                       A + (m0 + r) * KTOT + kc * 32 + cc);
        }
#pragma unroll
        for (int t = 0; t < 4; t++) {
            int idx = tid + t * 256;
            int r = idx >> 5, cc = (idx & 31) * 4;
            cp_async16(bs_u + (uint32_t)(s * GEMM_BSZ + r * BS_STRIDE + cc) * 4,
                       W + (size_t)(kc * 32 + r) * NTOT + n0 + cc);
        }
        asm volatile("cp.async.commit_group;" ::: "memory");
    };

    float c[2][8][4];
#pragma unroll
    for (int i = 0; i < 2; i++)
#pragma unroll
        for (int j = 0; j < 8; j++)
#pragma unroll
            for (int q = 0; q < 4; q++) c[i][j][q] = 0.0f;

    load_chunk(0, 0);
    for (int kc = 0; kc < NC; kc++) {
        int s = kc & 1;
        if (kc + 1 < NC) {
            load_chunk(kc + 1, (kc + 1) & 1);
            asm volatile("cp.async.wait_group 1;" ::: "memory");
        } else {
            asm volatile("cp.async.wait_group 0;" ::: "memory");
        }
        __syncthreads();
        const float* Ap = As + s * GEMM_ASZ;
        const float* Bp = Bs + s * GEMM_BSZ;
#pragma unroll
        for (int kb = 0; kb < 4; kb++) {
            uint32_t a[2][4], b[8][2];
#pragma unroll
            for (int i = 0; i < 2; i++) {
                int row = wr * 32 + i * 16 + g;
                a[i][0] = __float_as_uint(Ap[row * AS_STRIDE + kb * 8 + tg]);
                a[i][1] = __float_as_uint(Ap[(row + 8) * AS_STRIDE + kb * 8 + tg]);
                a[i][2] = __float_as_uint(Ap[row * AS_STRIDE + kb * 8 + tg + 4]);
                a[i][3] = __float_as_uint(Ap[(row + 8) * AS_STRIDE + kb * 8 + tg + 4]);
            }
#pragma unroll
            for (int j = 0; j < 8; j++) {
                int n = wc * 64 + j * 8 + g;
                b[j][0] = __float_as_uint(Bp[(kb * 8 + tg) * BS_STRIDE + n]);
                b[j][1] = __float_as_uint(Bp[(kb * 8 + tg + 4) * BS_STRIDE + n]);
            }
#pragma unroll
            for (int i = 0; i < 2; i++)
#pragma unroll
                for (int j = 0; j < 8; j++)
                    mma_tf32(c[i][j], a[i], b[j]);
        }
        __syncthreads();
    }

    // ---- epilogue ----
#pragma unroll
    for (int i = 0; i < 2; i++) {
#pragma unroll
        for (int half = 0; half < 2; half++) {
            size_t grow = m0 + wr * 32 + i * 16 + g + half * 8;
            float* dst = nullptr;
            int f = 0;
            if constexpr (EPI == 0 || EPI == 2) {
                dst = out + grow * NTOT;
            } else if constexpr (EPI == 1) {
                f = g_mflag[grow];
                dst = (f == 1) ? (g_att + (size_t)g_mrank[grow] * C_DIM)
                               : (out + (size_t)g_mrow[grow] * C_DIM);
            } else {
                dst = out + (size_t)g_asyrow[grow] * C_DIM;
            }
#pragma unroll
            for (int j = 0; j < 8; j++) {
                int colg = n0 + wc * 64 + j * 8 + tg * 2;
                float v0 = c[i][j][half * 2]     + __ldg(&bias[colg]);
                float v1 = c[i][j][half * 2 + 1] + __ldg(&bias[colg + 1]);
                if constexpr (EPI == 2) {
                    v0 = 0.5f * v0 * (1.0f + erff(v0 * 0.7071067811865476f));
                    v1 = 0.5f * v1 * (1.0f + erff(v1 * 0.7071067811865476f));
                }
                if constexpr (EPI == 3) {
                    v0 = g_y[grow * C_DIM + colg]     + __ldg(&evec[colg]) * v0;
                    v1 = g_y[grow * C_DIM + colg + 1] + __ldg(&evec[colg + 1]) * v1;
                }
                if constexpr (EPI == 1) {
                    if (f != 2)
                        *reinterpret_cast<float2*>(dst + colg) = make_float2(v0, v1);
                } else {
                    *reinterpret_cast<float2*>(dst + colg) = make_float2(v0, v1);
                }
            }
        }
    }
}

// ---------------------------------------------------------------------------
// K7: tensor-core attention per partition.  g_qkv (64x384) -> g_o (64x128).
//   8 warps; warp (h = wid>>1, half = wid&1) owns 32 rows of head h.
//   S = Q K^T via mma, register softmax (quad shuffles), P@V via mma.
// ---------------------------------------------------------------------------
#define QS3 388
#define SS3 66
#define ATTN3_SMEM_BYTES ((64 * QS3 + 4 * 64 * SS3) * 4 + 256)

__global__ void __launch_bounds__(256, 1) attn3_kernel(
    const float* __restrict__ gqkv, float* __restrict__ go)
{
    extern __shared__ float sm[];
    float* qsm = sm;                         // 64 x QS3
    float* ssm = sm + 64 * QS3;              // 4 heads x 64 x SS3
    int* kfl   = (int*)(ssm + 4 * 64 * SS3); // 64

    int m   = blockIdx.x;
    int tid = threadIdx.x;
    if (tid < 64) kfl[tid] = g_mflag[m * 64 + tid];

    const float4* src = reinterpret_cast<const float4*>(gqkv + (size_t)m * 64 * 384);
    for (int i = tid; i < 6144; i += 256) {
        int r = i / 96, c4 = (i - r * 96) * 4;
        *reinterpret_cast<float4*>(&qsm[r * QS3 + c4]) = src[i];
    }
    __syncthreads();

    int wid = tid >> 5, lane = tid & 31;
    int g = lane >> 2, tg = lane & 3;
    int h = wid >> 1;
    int rbase = (wid & 1) * 32;
    int bq = h * 96, bk = bq + 32, bv = bq + 64;
    float* ssh = ssm + h * 64 * SS3;
    const float scale = 0.17677669529663687f;

    // ---- S = Q K^T (32 rows x 64 cols, k = 32) ----
    float c[2][8][4];
#pragma unroll
    for (int i = 0; i < 2; i++)
#pragma unroll
        for (int j = 0; j < 8; j++)
#pragma unroll
            for (int q = 0; q < 4; q++) c[i][j][q] = 0.0f;

#pragma unroll
    for (int kt = 0; kt < 4; kt++) {
        uint32_t a[2][4], b[8][2];
#pragma unroll
        for (int i = 0; i < 2; i++) {
            int row = rbase + i * 16 + g;
            a[i][0] = __float_as_uint(qsm[row * QS3 + bq + kt * 8 + tg]);
            a[i][1] = __float_as_uint(qsm[(row + 8) * QS3 + bq + kt * 8 + tg]);
            a[i][2] = __float_as_uint(qsm[row * QS3 + bq + kt * 8 + tg + 4]);
            a[i][3] = __float_as_uint(qsm[(row + 8) * QS3 + bq + kt * 8 + tg + 4]);
        }
#pragma unroll
        for (int j = 0; j < 8; j++) {
            int n = j * 8 + g;
            b[j][0] = __float_as_uint(qsm[n * QS3 + bk + kt * 8 + tg]);
            b[j][1] = __float_as_uint(qsm[n * QS3 + bk + kt * 8 + tg + 4]);
        }
#pragma unroll
        for (int i = 0; i < 2; i++)
#pragma unroll
            for (int j = 0; j < 8; j++)
                mma_tf32(c[i][j], a[i], b[j]);
    }

    // ---- mask bits (per thread: 16 columns) ----
    unsigned mask = 0;
#pragma unroll
    for (int j = 0; j < 8; j++)
#pragma unroll
        for (int q = 0; q < 2; q++)
            if (kfl[j * 8 + 2 * tg + q] == 2) mask |= 1u << (j * 2 + q);

    // ---- register softmax per row (row = quad of threads, shfl 1,2) ----
#pragma unroll
    for (int i = 0; i < 2; i++) {
#pragma unroll
        for (int sel = 0; sel < 2; sel++) {
            float mx = -1e30f;
#pragma unroll
            for (int j = 0; j < 8; j++)
#pragma unroll
                for (int q = 0; q < 2; q++) {
                    float v = c[i][j][sel * 2 + q] * scale;
                    if (mask & (1u << (j * 2 + q))) v = -10000.0f;
                    c[i][j][sel * 2 + q] = v;
                    mx = fmaxf(mx, v);
                }
            mx = fmaxf(mx, __shfl_xor_sync(0xffffffffu, mx, 1));
            mx = fmaxf(mx, __shfl_xor_sync(0xffffffffu, mx, 2));
            float s = 0.0f;
#pragma unroll
            for (int j = 0; j < 8; j++)
#pragma unroll
                for (int q = 0; q < 2; q++) {
                    float e = __expf(c[i][j][sel * 2 + q] - mx);
                    c[i][j][sel * 2 + q] = e;
                    s += e;
                }
            s += __shfl_xor_sync(0xffffffffu, s, 1);
            s += __shfl_xor_sync(0xffffffffu, s, 2);
            float rinv = 1.0f / s;
            int row = rbase + i * 16 + g + sel * 8;
#pragma unroll
            for (int j = 0; j < 8; j++)
#pragma unroll
                for (int q = 0; q < 2; q++)
                    ssh[row * SS3 + j * 8 + 2 * tg + q] = c[i][j][sel * 2 + q] * rinv;
        }
    }
    __syncwarp();

    // ---- O = P @ V (32 rows x 32 cols, k = 64) ----
    float o[2][4][4];
#pragma unroll
    for (int i = 0; i < 2; i++)
#pragma unroll
        for (int j = 0; j < 4; j++)
#pragma unroll
            for (int q = 0; q < 4; q++) o[i][j][q] = 0.0f;

#pragma unroll
    for (int kt = 0; kt < 8; kt++) {
        uint32_t a[2][4], b[4][2];
#pragma unroll
        for (int i = 0; i < 2; i++) {
            int row = rbase + i * 16 + g;
            a[i][0] = __float_as_uint(ssh[row * SS3 + kt * 8 + tg]);
            a[i][1] = __float_as_uint(ssh[(row + 8) * SS3 + kt * 8 + tg]);
            a[i][2] = __float_as_uint(ssh[row * SS3 + kt * 8 + tg + 4]);
            a[i][3] = __float_as_uint(ssh[(row + 8) * SS3 + kt * 8 + tg + 4]);
        }
#pragma unroll
        for (int j = 0; j < 4; j++) {
            int n = j * 8 + g;
            b[j][0] = __float_as_uint(qsm[(kt * 8 + tg) * QS3 + bv + n]);
            b[j][1] = __float_as_uint(qsm[(kt * 8 + tg + 4) * QS3 + bv + n]);
        }
#pragma unroll
        for (int i = 0; i < 2; i++)
#pragma unroll
            for (int j = 0; j < 4; j++)
                mma_tf32(o[i][j], a[i], b[j]);
    }

#pragma unroll
    for (int i = 0; i < 2; i++)
#pragma unroll
        for (int j = 0; j < 4; j++) {
            size_t row = (size_t)(m * 64 + rbase + i * 16 + g);
            int col = h * 32 + j * 8 + 2 * tg;
            *reinterpret_cast<float2*>(&go[row * C_DIM + col]) =
                make_float2(o[i][j][0], o[i][j][1]);
            *reinterpret_cast<float2*>(&go[(row + 8) * C_DIM + col]) =
                make_float2(o[i][j][2], o[i][j][3]);
        }
}

// ---------------------------------------------------------------------------
// K8: y = xa + g1*att -> g_y ; g_yn = LN2(y).
// ---------------------------------------------------------------------------
__global__ void __launch_bounds__(256) ybuild_kernel(
    const float* __restrict__ g1,
    const float* __restrict__ ln2w, const float* __restrict__ ln2b)
{
    int r    = (int)((blockIdx.x * 256u + threadIdx.x) >> 5);
    int lane = threadIdx.x & 31;
    if (r >= A_CNT) return;
    float4 a = reinterpret_cast<const float4*>(g_xa + (size_t)r * C_DIM)[lane];
    float4 t = reinterpret_cast<const float4*>(g_att + (size_t)r * C_DIM)[lane];
    float4 gv = reinterpret_cast<const float4*>(g1)[lane];
    float4 y;
    y.x = a.x + gv.x * t.x; y.y = a.y + gv.y * t.y;
    y.z = a.z + gv.z * t.z; y.w = a.w + gv.w * t.w;
    reinterpret_cast<float4*>(g_y + (size_t)r * C_DIM)[lane] = y;
    float m = warp_sum(y.x + y.y + y.z + y.w) * (1.0f / C_DIM);
    float dx = y.x - m, dy = y.y - m, dz = y.z - m, dw = y.w - m;
    float var = warp_sum(dx*dx + dy*dy + dz*dz + dw*dw) * (1.0f / C_DIM);
    float inv = rsqrtf(var + EPS_LN);
    float4 wv = reinterpret_cast<const float4*>(ln2w)[lane];
    float4 bv = reinterpret_cast<const float4*>(ln2b)[lane];
    float4 o;
    o.x = dx * inv * wv.x + bv.x; o.y = dy * inv * wv.y + bv.y;
    o.z = dz * inv * wv.z + bv.z; o.w = dw * inv * wv.w + bv.w;
    reinterpret_cast<float4*>(g_yn + (size_t)r * C_DIM)[lane] = o;
}

// ---------------------------------------------------------------------------
extern "C" void kernel_launch(void* const* d_in, const int* in_sizes, int n_in,
                              void* d_out, int out_size)
{
    int base = 7;
    if (n_in == 19) base = 5;

    const float* x      = (const float*)d_in[0];
    const int*   iw     = (const int*)d_in[1];
    const int*   ipart  = (const int*)d_in[2];
    const int*   asy    = (const int*)d_in[3];
    const int*   blk    = (const int*)d_in[4];
    const float* ln1w   = (const float*)d_in[base + 0];
    const float* ln1b   = (const float*)d_in[base + 1];
    const float* qkvw   = (const float*)d_in[base + 2];
    const float* qkvb   = (const float*)d_in[base + 3];
    const float* projw  = (const float*)d_in[base + 4];
    const float* projb  = (const float*)d_in[base + 5];
    const float* g1     = (const float*)d_in[base + 6];
    const float* ln2w   = (const float*)d_in[base + 7];
    const float* ln2b   = (const float*)d_in[base + 8];
    const float* w1     = (const float*)d_in[base + 9];
    const float* b1     = (const float*)d_in[base + 10];
    const float* w2     = (const float*)d_in[base + 11];
    const float* b2     = (const float*)d_in[base + 12];
    const float* g2     = (const float*)d_in[base + 13];
    float* out = (float*)d_out;

    float *p_xp, *p_qkv, *p_o, *p_yn, *p_h;
    cudaGetSymbolAddress((void**)&p_xp, g_xp);
    cudaGetSymbolAddress((void**)&p_qkv, g_qkv);
    cudaGetSymbolAddress((void**)&p_o, g_o);
    cudaGetSymbolAddress((void**)&p_yn, g_yn);
    cudaGetSymbolAddress((void**)&p_h, g_h);

    cudaFuncSetAttribute(gemm2_kernel<384, 128, 0>,
                         cudaFuncAttributeMaxDynamicSharedMemorySize, GEMM_SMEM_BYTES);
    cudaFuncSetAttribute(gemm2_kernel<128, 128, 1>,
                         cudaFuncAttributeMaxDynamicSharedMemorySize, GEMM_SMEM_BYTES);
    cudaFuncSetAttribute(gemm2_kernel<512, 128, 2>,
                         cudaFuncAttributeMaxDynamicSharedMemorySize, GEMM_SMEM_BYTES);
    cudaFuncSetAttribute(gemm2_kernel<128, 512, 3>,
                         cudaFuncAttributeMaxDynamicSharedMemorySize, GEMM_SMEM_BYTES);
    cudaFuncSetAttribute(attn3_kernel,
                         cudaFuncAttributeMaxDynamicSharedMemorySize, ATTN3_SMEM_BYTES);

    // 1. X = LN(x)
    ln_kernel<<<N_TOK / 8, 256>>>(x, ln1w, ln1b, out);
    // 2-3. flag/rank maps
    zero_flags_kernel<<<(MW_CNT / 16 + 255) / 256, 256>>>();
    set_flags_kernel<<<(A_CNT + BL_CNT + 255) / 256, 256>>>(asy, blk, iw);
    // 4. xa double-LN
    xa_kernel<<<A_CNT / 8, 256>>>(out, asy, iw, ln1w, ln1b);
    // 5. gather attention input + meta
    gather_kernel<<<MW_CNT / 8, 256>>>(out, ipart, iw);
    // 6. QKV GEMM
    gemm2_kernel<384, 128, 0><<<dim3(MW_CNT / 128, 3), 256, GEMM_SMEM_BYTES>>>(
        p_xp, qkvw, qkvb, p_qkv, nullptr);
    // 7. attention (tensor cores)
    attn3_kernel<<<M_PART, 256, ATTN3_SMEM_BYTES>>>(p_qkv, p_o);
    // 8. proj GEMM + scatter
    gemm2_kernel<128, 128, 1><<<dim3(MW_CNT / 128, 1), 256, GEMM_SMEM_BYTES>>>(
        p_o, projw, projb, out, nullptr);
    // 9. y build + LN2
    ybuild_kernel<<<A_CNT / 8, 256>>>(g1, ln2w, ln2b);
    // 10. MLP GEMM1 + gelu
    gemm2_kernel<512, 128, 2><<<dim3(A_CNT / 128, 4), 256, GEMM_SMEM_BYTES>>>(
        p_yn, w1, b1, p_h, nullptr);
    // 11. MLP GEMM2 + residual + scatter
    gemm2_kernel<128, 512, 3><<<dim3(A_CNT / 128, 1), 256, GEMM_SMEM_BYTES>>>(
        p_h, w2, b2, out, g2);
}